// round 13
// baseline (speedup 1.0000x reference)
#include <cuda_runtime.h>

// SSIM map: 3x3 mean filter (reflect pad 1) fused, fp32 in/out.
// R10 base (8-wide per-thread tiles) + distance-1 software pipeline:
// 4-slot rotating register buffer, row i+2 loaded during iteration i,
// consumed in iteration i+1 (a full iteration of latency slack, no copies).
// Shapes fixed: planes=96, H=384, W=640.

#define HH 384
#define WW 640
#define STRIP 8            // output rows per thread
#define TPW 80             // threads per row-strip: 80 * 8 cols = 640
#define ROWS_PER_BLK 2     // row-strips per block
#define TPB (TPW * ROWS_PER_BLK)   // 160 threads

__device__ __forceinline__ int rrow(int r) {
    // reflect index for pad=1: -1 -> 1, H -> H-2
    return r < 0 ? -r : (r >= HH ? 2 * HH - 2 - r : r);
}

// Load 10 columns (c0-1 .. c0+8) of one row.
__device__ __forceinline__ void load_row10(const float* __restrict__ base,
                                           int c0, int cm1, int cp8,
                                           float d[10]) {
    float4 v = *(const float4*)(base + c0);
    float4 w = *(const float4*)(base + c0 + 4);
    d[0] = __ldg(base + cm1);
    d[1] = v.x; d[2] = v.y; d[3] = v.z; d[4] = v.w;
    d[5] = w.x; d[6] = w.y; d[7] = w.z; d[8] = w.w;
    d[9] = __ldg(base + cp8);
}

__global__ __launch_bounds__(TPB)
void ssim_kernel(const float* __restrict__ x,
                 const float* __restrict__ y,
                 float* __restrict__ out)
{
    const int tid   = threadIdx.x;
    const int tx    = tid % TPW;
    const int ty    = tid / TPW;
    const int c0    = tx * 8;
    const int plane = blockIdx.y;
    const int r0    = (blockIdx.x * ROWS_PER_BLK + ty) * STRIP;

    const size_t pbase = (size_t)plane * HH * WW;
    const float* xp = x + pbase;
    const float* yp = y + pbase;
    float* op       = out + pbase;

    const int cm1 = (c0 == 0) ? 1 : c0 - 1;
    const int cp8 = (c0 + 8 >= WW) ? (WW - 2) : (c0 + 8);

    // Rescaled constants: num and den both carry x81^2, which cancels.
    const float C1S = 81.0f * 1.0e-4f;   // 81*C1
    const float C2S = 81.0f * 9.0e-4f;   // 81*C2

    // 4-slot rotating register buffers: 10 columns (c0-1 .. c0+8), x and y.
    // Slot (i+3)%4 is loaded during iteration i (row r0+i+2) and first
    // consumed during iteration i+1 -> one full iteration of load slack.
    float xr[4][10], yr[4][10];

    // Preload rows r0-1, r0, r0+1 into slots 0,1,2.
    #pragma unroll
    for (int k = 0; k < 3; k++) {
        const int r = rrow(r0 - 1 + k);
        load_row10(xp + (size_t)r * WW, c0, cm1, cp8, xr[k]);
        load_row10(yp + (size_t)r * WW, c0, cm1, cp8, yr[k]);
    }

    #pragma unroll
    for (int i = 0; i < STRIP; i++) {
        // ---- Prefetch row r0+i+2 into slot (i+3)%4 (used NEXT iteration).
        //      Skipped on the last iteration (row would be unused). ----
        if (i < STRIP - 1) {
            const int slot = (i + 3) % 4;
            const int r = rrow(r0 + i + 2);
            load_row10(xp + (size_t)r * WW, c0, cm1, cp8, xr[slot]);
            load_row10(yp + (size_t)r * WW, c0, cm1, cp8, yr[slot]);
        }

        const int s0 = i % 4, s1 = (i + 1) % 4, s2 = (i + 2) % 4;

        // ---- Vertical (column) sums over 3 rows for all 10 columns ----
        float sx[10], sy[10], sxx[10], syy[10], sxy[10];
        #pragma unroll
        for (int j = 0; j < 10; j++) {
            const float a0 = xr[s0][j], a1 = xr[s1][j], a2 = xr[s2][j];
            const float b0 = yr[s0][j], b1 = yr[s1][j], b2 = yr[s2][j];
            sx[j]  = a0 + a1 + a2;
            sy[j]  = b0 + b1 + b2;
            sxx[j] = fmaf(a0, a0, fmaf(a1, a1, a2 * a2));
            syy[j] = fmaf(b0, b0, fmaf(b1, b1, b2 * b2));
            sxy[j] = fmaf(a0, b0, fmaf(a1, b1, a2 * b2));
        }

        // ---- Horizontal 3-sums via shared pair-sums (12 adds per stat) ----
        float Sx[8], Sy[8], Sxx[8], Syy[8], Sxy[8];
        #define H8(S, s) { \
            const float u1 = s[1]+s[2], u3 = s[3]+s[4], u5 = s[5]+s[6], u7 = s[7]+s[8]; \
            S[0] = s[0]+u1; S[1] = u1+s[3]; S[2] = s[2]+u3; S[3] = u3+s[5]; \
            S[4] = s[4]+u5; S[5] = u5+s[7]; S[6] = s[6]+u7; S[7] = u7+s[9]; }
        H8(Sx,  sx);  H8(Sy,  sy);
        H8(Sxx, sxx); H8(Syy, syy); H8(Sxy, sxy);
        #undef H8

        // ---- SSIM, rescaled by 81^2 (cancels in the ratio) ----
        float resv[8];
        #pragma unroll
        for (int o = 0; o < 8; o++) {
            const float P  = Sx[o] * Sy[o];
            const float Qx = Sx[o] * Sx[o];
            const float Qy = Sy[o] * Sy[o];
            const float A  = fmaf(Sxx[o], 9.0f, -Qx);   // 9*Sxx - Sx^2 (FFMA-imm)
            const float B  = fmaf(Syy[o], 9.0f, -Qy);
            const float Cc = fmaf(Sxy[o], 9.0f, -P);
            const float num = fmaf(P, 2.0f, C1S) * fmaf(Cc, 2.0f, C2S);
            const float den = (Qx + Qy + C1S) * (A + B + C2S);
            float s = __fdividef(num, den);
            resv[o] = fminf(fmaxf(s, 0.0f), 1.0f);
        }

        float* orow = op + (size_t)(r0 + i) * WW + c0;
        *(float4*)(orow)     = make_float4(resv[0], resv[1], resv[2], resv[3]);
        *(float4*)(orow + 4) = make_float4(resv[4], resv[5], resv[6], resv[7]);
    }
}

extern "C" void kernel_launch(void* const* d_in, const int* in_sizes, int n_in,
                              void* d_out, int out_size) {
    const float* x = (const float*)d_in[0];
    const float* y = (const float*)d_in[1];
    float* out = (float*)d_out;

    const int planes = in_sizes[0] / (HH * WW);          // 96
    dim3 grid(HH / (STRIP * ROWS_PER_BLK), planes);      // (24, 96)
    ssim_kernel<<<grid, TPB>>>(x, y, out);
}

// round 14
// speedup vs baseline: 1.1147x; 1.1147x over previous
#include <cuda_runtime.h>

// SSIM map: 3x3 mean (reflect pad 1), fp32. cp.async smem row-ring pipeline:
// 6-row shared ring, prefetch distance 4 rows (latency decoupled from both
// registers and occupancy). Proven R8 compute body, 4 cols/thread.
// Shapes fixed: planes=96, H=384, W=640.

#define HH 384
#define WW 640
#define CHUNK 24          // output rows per block
#define RING 6            // smem ring slots (rows)
#define DIST 4            // prefetch distance in rows
#define TPB 160           // 160 threads * 4 cols = 640

__device__ __forceinline__ int rrow(int r) {
    return r < 0 ? -r : (r >= HH ? 2 * HH - 2 - r : r);
}

__device__ __forceinline__ void cp16(float* s, const float* g) {
    unsigned sa = (unsigned)__cvta_generic_to_shared(s);
    asm volatile("cp.async.ca.shared.global [%0], [%1], 16;" :: "r"(sa), "l"(g));
}
__device__ __forceinline__ void cp_commit() {
    asm volatile("cp.async.commit_group;");
}
__device__ __forceinline__ void cp_wait2() {
    asm volatile("cp.async.wait_group 2;");
}

__global__ __launch_bounds__(TPB)
void ssim_kernel(const float* __restrict__ x,
                 const float* __restrict__ y,
                 float* __restrict__ out)
{
    __shared__ float xs[RING][WW];
    __shared__ float ys[RING][WW];

    const int tid   = threadIdx.x;
    const int c0    = tid * 4;
    const int plane = blockIdx.y;
    const int r0    = blockIdx.x * CHUNK;

    const size_t pbase = (size_t)plane * HH * WW;
    const float* xp = x + pbase;
    const float* yp = y + pbase;
    float* op       = out + pbase;

    // Column reflect (full row in smem, so halo columns are just indices).
    const int cm1 = (c0 == 0) ? 1 : c0 - 1;
    const int cp4 = (c0 + 4 >= WW) ? (WW - 2) : (c0 + 4);

    const float C1S = 81.0f * 1.0e-4f;   // 81*C1 (x81^2 rescale cancels)
    const float C2S = 81.0f * 9.0e-4f;   // 81*C2

    // ---- Prologue: issue input rows k=0..DIST-1 (globals r0-1+k) ----
    #pragma unroll
    for (int k = 0; k < DIST; k++) {
        const int r = rrow(r0 - 1 + k);
        cp16(&xs[k][c0], xp + (size_t)r * WW + c0);
        cp16(&ys[k][c0], yp + (size_t)r * WW + c0);
        cp_commit();
    }
    cp_wait2();          // rows k=0,1 complete (<=2 groups outstanding)
    __syncthreads();

    // 3-row register rotation, seeded with rows k=0,1 (slots 0,1).
    float xr[3][6], yr[3][6];
    #pragma unroll
    for (int k = 0; k < 2; k++) {
        float4 v = *(const float4*)(&xs[k][c0]);
        xr[k][0] = xs[k][cm1];
        xr[k][1] = v.x; xr[k][2] = v.y; xr[k][3] = v.z; xr[k][4] = v.w;
        xr[k][5] = xs[k][cp4];
        float4 w = *(const float4*)(&ys[k][c0]);
        yr[k][0] = ys[k][cm1];
        yr[k][1] = w.x; yr[k][2] = w.y; yr[k][3] = w.z; yr[k][4] = w.w;
        yr[k][5] = ys[k][cp4];
    }

    // ---- Main loop: CHUNK rows, 6x inner unroll keeps all mods static ----
    #pragma unroll 1
    for (int ii = 0; ii < CHUNK; ii += 6) {
        #pragma unroll
        for (int u = 0; u < 6; u++) {
            const int i = ii + u;

            // Issue input row k=i+DIST (clamped; overshoot writes land in
            // slots never consumed again). Write slot disjoint from the
            // read slots of iterations i-1, i (distance 3..5 mod 6).
            {
                const int k  = i + DIST;
                const int kc = (k <= CHUNK + 1) ? k : (CHUNK + 1);
                const int ws = (u + DIST) % RING;       // static
                const int r  = rrow(r0 - 1 + kc);
                cp16(&xs[ws][c0], xp + (size_t)r * WW + c0);
                cp16(&ys[ws][c0], yp + (size_t)r * WW + c0);
                cp_commit();
            }
            cp_wait2();              // row k=i+2 complete
            __syncthreads();         // ...and visible from all threads

            // Read the one new row (k=i+2) from its ring slot.
            {
                const int rs  = (u + 2) % RING;         // static
                const int dst = (u + 2) % 3;            // static
                float4 v = *(const float4*)(&xs[rs][c0]);
                xr[dst][0] = xs[rs][cm1];
                xr[dst][1] = v.x; xr[dst][2] = v.y; xr[dst][3] = v.z; xr[dst][4] = v.w;
                xr[dst][5] = xs[rs][cp4];
                float4 w = *(const float4*)(&ys[rs][c0]);
                yr[dst][0] = ys[rs][cm1];
                yr[dst][1] = w.x; yr[dst][2] = w.y; yr[dst][3] = w.z; yr[dst][4] = w.w;
                yr[dst][5] = ys[rs][cp4];
            }

            const int s0 = u % 3, s1 = (u + 1) % 3, s2 = (u + 2) % 3;

            // ---- Vertical sums over 3 rows, 6 columns ----
            float sx[6], sy[6], sxx[6], syy[6], sxy[6];
            #pragma unroll
            for (int j = 0; j < 6; j++) {
                const float a0 = xr[s0][j], a1 = xr[s1][j], a2 = xr[s2][j];
                const float b0 = yr[s0][j], b1 = yr[s1][j], b2 = yr[s2][j];
                sx[j]  = a0 + a1 + a2;
                sy[j]  = b0 + b1 + b2;
                sxx[j] = fmaf(a0, a0, fmaf(a1, a1, a2 * a2));
                syy[j] = fmaf(b0, b0, fmaf(b1, b1, b2 * b2));
                sxy[j] = fmaf(a0, b0, fmaf(a1, b1, a2 * b2));
            }

            // ---- Horizontal 3-sums via shared sub-sums ----
            float Sx[4], Sy[4], Sxx[4], Syy[4], Sxy[4];
            {
                float u1, v1;
                u1 = sx[1] + sx[2];   v1 = sx[3] + sx[4];
                Sx[0] = sx[0] + u1;  Sx[1] = u1 + sx[3];  Sx[2] = sx[2] + v1;  Sx[3] = v1 + sx[5];
                u1 = sy[1] + sy[2];   v1 = sy[3] + sy[4];
                Sy[0] = sy[0] + u1;  Sy[1] = u1 + sy[3];  Sy[2] = sy[2] + v1;  Sy[3] = v1 + sy[5];
                u1 = sxx[1] + sxx[2]; v1 = sxx[3] + sxx[4];
                Sxx[0] = sxx[0] + u1; Sxx[1] = u1 + sxx[3]; Sxx[2] = sxx[2] + v1; Sxx[3] = v1 + sxx[5];
                u1 = syy[1] + syy[2]; v1 = syy[3] + syy[4];
                Syy[0] = syy[0] + u1; Syy[1] = u1 + syy[3]; Syy[2] = syy[2] + v1; Syy[3] = v1 + syy[5];
                u1 = sxy[1] + sxy[2]; v1 = sxy[3] + sxy[4];
                Sxy[0] = sxy[0] + u1; Sxy[1] = u1 + sxy[3]; Sxy[2] = sxy[2] + v1; Sxy[3] = v1 + sxy[5];
            }

            // ---- SSIM, rescaled by 81^2 ----
            float resv[4];
            #pragma unroll
            for (int o = 0; o < 4; o++) {
                const float P  = Sx[o] * Sy[o];
                const float Qx = Sx[o] * Sx[o];
                const float Qy = Sy[o] * Sy[o];
                const float A  = fmaf(Sxx[o], 9.0f, -Qx);
                const float B  = fmaf(Syy[o], 9.0f, -Qy);
                const float Cc = fmaf(Sxy[o], 9.0f, -P);
                const float num = fmaf(P, 2.0f, C1S) * fmaf(Cc, 2.0f, C2S);
                const float den = (Qx + Qy + C1S) * (A + B + C2S);
                float s = __fdividef(num, den);
                resv[o] = fminf(fmaxf(s, 0.0f), 1.0f);
            }

            // Streaming store (evict-first: keep L2 for row-halo reuse).
            __stcs((float4*)(op + (size_t)(r0 + i) * WW + c0),
                   make_float4(resv[0], resv[1], resv[2], resv[3]));
        }
    }
}

extern "C" void kernel_launch(void* const* d_in, const int* in_sizes, int n_in,
                              void* d_out, int out_size) {
    const float* x = (const float*)d_in[0];
    const float* y = (const float*)d_in[1];
    float* out = (float*)d_out;

    const int planes = in_sizes[0] / (HH * WW);   // 96
    dim3 grid(HH / CHUNK, planes);                // (16, 96)
    ssim_kernel<<<grid, TPB>>>(x, y, out);
}

// round 16
// speedup vs baseline: 1.2031x; 1.0793x over previous
#include <cuda_runtime.h>

// SSIM map: 3x3 mean (reflect pad 1), fp32. cp.async smem row-ring,
// TWO output rows per pipeline step (half the barriers/waits), pair-shared
// vertical sums, guarded tail issues with empty commit groups.
// Shapes fixed: planes=96, H=384, W=640.

#define HH 384
#define WW 640
#define CHUNK 24           // output rows per block
#define NSTEP (CHUNK / 2)  // 12 pipeline steps (2 rows each)
#define RING 8             // smem ring slots (rows)
#define TPB 160            // 160 threads * 4 cols = 640

__device__ __forceinline__ int rrow(int r) {
    return r < 0 ? -r : (r >= HH ? 2 * HH - 2 - r : r);
}

__device__ __forceinline__ void cp16(float* s, const float* g) {
    unsigned sa = (unsigned)__cvta_generic_to_shared(s);
    asm volatile("cp.async.ca.shared.global [%0], [%1], 16;" :: "r"(sa), "l"(g));
}
__device__ __forceinline__ void cp_commit() {
    asm volatile("cp.async.commit_group;");
}
__device__ __forceinline__ void cp_wait1() {
    asm volatile("cp.async.wait_group 1;");
}

__global__ __launch_bounds__(TPB)
void ssim_kernel(const float* __restrict__ x,
                 const float* __restrict__ y,
                 float* __restrict__ out)
{
    __shared__ float xs[RING][WW];
    __shared__ float ys[RING][WW];

    const int tid   = threadIdx.x;
    const int c0    = tid * 4;
    const int plane = blockIdx.y;
    const int r0    = blockIdx.x * CHUNK;

    const size_t pbase = (size_t)plane * HH * WW;
    const float* xp = x + pbase;
    const float* yp = y + pbase;
    float* op       = out + pbase;

    const int cm1 = (c0 == 0) ? 1 : c0 - 1;
    const int cp4 = (c0 + 4 >= WW) ? (WW - 2) : (c0 + 4);

    const float C1S = 81.0f * 1.0e-4f;   // 81*C1 (x81^2 rescale cancels)
    const float C2S = 81.0f * 9.0e-4f;   // 81*C2

    // ---- Prologue: issue groups g=0..2 (rows k=2g, 2g+1; slot=k) ----
    #pragma unroll
    for (int g = 0; g < 3; g++) {
        #pragma unroll
        for (int rr = 0; rr < 2; rr++) {
            const int k = 2 * g + rr;
            const int r = rrow(r0 - 1 + k);
            cp16(&xs[k][c0], xp + (size_t)r * WW + c0);
            cp16(&ys[k][c0], yp + (size_t)r * WW + c0);
        }
        cp_commit();
    }
    cp_wait1();              // groups 0,1 done -> rows k=0..3 in smem
    __syncthreads();

    // 4-row register rotation (raw values), reg slot = k % 4.
    float xr[4][6], yr[4][6];
    #pragma unroll
    for (int k = 0; k < 2; k++) {
        float4 v = *(const float4*)(&xs[k][c0]);
        xr[k][0] = xs[k][cm1];
        xr[k][1] = v.x; xr[k][2] = v.y; xr[k][3] = v.z; xr[k][4] = v.w;
        xr[k][5] = xs[k][cp4];
        float4 w = *(const float4*)(&ys[k][c0]);
        yr[k][0] = ys[k][cm1];
        yr[k][1] = w.x; yr[k][2] = w.y; yr[k][3] = w.z; yr[k][4] = w.w;
        yr[k][5] = ys[k][cp4];
    }

    // ---- Main: 12 steps, 4-step unroll keeps every slot index static ----
    #pragma unroll 1
    for (int tt = 0; tt < NSTEP; tt += 4) {
        #pragma unroll
        for (int u = 0; u < 4; u++) {
            const int t = tt + u;

            // Wait: groups <= t+1 complete (rows k <= 2t+3 in smem).
            cp_wait1();
            __syncthreads();

            // Issue group t+3 (rows k=2t+6, 2t+7 -> slots (2u+6)%8,(2u+7)%8).
            // Guarded for the tail; ALWAYS commit so group counts stay aligned.
            {
                const int k0 = 2 * t + 6, k1 = 2 * t + 7;
                if (k0 <= CHUNK + 1) {
                    const int r = rrow(r0 - 1 + k0);
                    cp16(&xs[(2 * u + 6) % RING][c0], xp + (size_t)r * WW + c0);
                    cp16(&ys[(2 * u + 6) % RING][c0], yp + (size_t)r * WW + c0);
                }
                if (k1 <= CHUNK + 1) {
                    const int r = rrow(r0 - 1 + k1);
                    cp16(&xs[(2 * u + 7) % RING][c0], xp + (size_t)r * WW + c0);
                    cp16(&ys[(2 * u + 7) % RING][c0], yp + (size_t)r * WW + c0);
                }
                cp_commit();
            }

            // Pull rows k=2t+2, 2t+3 from smem into the register rotation.
            #pragma unroll
            for (int d = 0; d < 2; d++) {
                const int ss = (2 * u + 2 + d) % RING;   // static
                const int rs = (2 * u + 2 + d) % 4;      // static
                float4 v = *(const float4*)(&xs[ss][c0]);
                xr[rs][0] = xs[ss][cm1];
                xr[rs][1] = v.x; xr[rs][2] = v.y; xr[rs][3] = v.z; xr[rs][4] = v.w;
                xr[rs][5] = xs[ss][cp4];
                float4 w = *(const float4*)(&ys[ss][c0]);
                yr[rs][0] = ys[ss][cm1];
                yr[rs][1] = w.x; yr[rs][2] = w.y; yr[rs][3] = w.z; yr[rs][4] = w.w;
                yr[rs][5] = ys[ss][cp4];
            }

            // Register slots for input rows A=2t, B=2t+1, C=2t+2, D=2t+3.
            const int sA = (2 * u) % 4,     sB = (2 * u + 1) % 4;
            const int sC = (2 * u + 2) % 4, sD = (2 * u + 3) % 4;

            // ---- Pair-shared vertical sums (rows 2t and 2t+1) ----
            float sx0[6], sy0[6], sxx0[6], syy0[6], sxy0[6];   // output row 2t
            float sx1[6], sy1[6], sxx1[6], syy1[6], sxy1[6];   // output row 2t+1
            #pragma unroll
            for (int j = 0; j < 6; j++) {
                const float aA = xr[sA][j], aB = xr[sB][j], aC = xr[sC][j], aD = xr[sD][j];
                const float bA = yr[sA][j], bB = yr[sB][j], bC = yr[sC][j], bD = yr[sD][j];
                const float mx  = aB + aC;
                const float my  = bB + bC;
                const float mxx = fmaf(aB, aB, aC * aC);
                const float myy = fmaf(bB, bB, bC * bC);
                const float mxy = fmaf(aB, bB, aC * bC);
                sx0[j]  = aA + mx;              sx1[j]  = mx + aD;
                sy0[j]  = bA + my;              sy1[j]  = my + bD;
                sxx0[j] = fmaf(aA, aA, mxx);    sxx1[j] = fmaf(aD, aD, mxx);
                syy0[j] = fmaf(bA, bA, myy);    syy1[j] = fmaf(bD, bD, myy);
                sxy0[j] = fmaf(aA, bA, mxy);    sxy1[j] = fmaf(aD, bD, mxy);
            }

            // ---- Horizontal sums + epilogue, per output row ----
            #define ROW_OUT(sx, sy, sxx, syy, sxy, ROWI)                              \
            {                                                                          \
                float Sx[4], Sy[4], Sxx[4], Syy[4], Sxy[4];                            \
                {                                                                      \
                    float u1, v1;                                                      \
                    u1 = sx[1] + sx[2];   v1 = sx[3] + sx[4];                          \
                    Sx[0] = sx[0] + u1;  Sx[1] = u1 + sx[3];                           \
                    Sx[2] = sx[2] + v1;  Sx[3] = v1 + sx[5];                           \
                    u1 = sy[1] + sy[2];   v1 = sy[3] + sy[4];                          \
                    Sy[0] = sy[0] + u1;  Sy[1] = u1 + sy[3];                           \
                    Sy[2] = sy[2] + v1;  Sy[3] = v1 + sy[5];                           \
                    u1 = sxx[1] + sxx[2]; v1 = sxx[3] + sxx[4];                        \
                    Sxx[0] = sxx[0] + u1; Sxx[1] = u1 + sxx[3];                        \
                    Sxx[2] = sxx[2] + v1; Sxx[3] = v1 + sxx[5];                        \
                    u1 = syy[1] + syy[2]; v1 = syy[3] + syy[4];                        \
                    Syy[0] = syy[0] + u1; Syy[1] = u1 + syy[3];                        \
                    Syy[2] = syy[2] + v1; Syy[3] = v1 + syy[5];                        \
                    u1 = sxy[1] + sxy[2]; v1 = sxy[3] + sxy[4];                        \
                    Sxy[0] = sxy[0] + u1; Sxy[1] = u1 + sxy[3];                        \
                    Sxy[2] = sxy[2] + v1; Sxy[3] = v1 + sxy[5];                        \
                }                                                                      \
                float resv[4];                                                         \
                _Pragma("unroll")                                                      \
                for (int o = 0; o < 4; o++) {                                          \
                    const float P  = Sx[o] * Sy[o];                                    \
                    const float Qx = Sx[o] * Sx[o];                                    \
                    const float Qy = Sy[o] * Sy[o];                                    \
                    const float A  = fmaf(Sxx[o], 9.0f, -Qx);                          \
                    const float B  = fmaf(Syy[o], 9.0f, -Qy);                          \
                    const float Cc = fmaf(Sxy[o], 9.0f, -P);                           \
                    const float num = fmaf(P, 2.0f, C1S) * fmaf(Cc, 2.0f, C2S);        \
                    const float den = (Qx + Qy + C1S) * (A + B + C2S);                 \
                    float s = __fdividef(num, den);                                    \
                    resv[o] = fminf(fmaxf(s, 0.0f), 1.0f);                             \
                }                                                                      \
                __stcs((float4*)(op + (size_t)(r0 + (ROWI)) * WW + c0),                \
                       make_float4(resv[0], resv[1], resv[2], resv[3]));               \
            }

            ROW_OUT(sx0, sy0, sxx0, syy0, sxy0, 2 * t);
            ROW_OUT(sx1, sy1, sxx1, syy1, sxy1, 2 * t + 1);
            #undef ROW_OUT
        }
    }
}

extern "C" void kernel_launch(void* const* d_in, const int* in_sizes, int n_in,
                              void* d_out, int out_size) {
    const float* x = (const float*)d_in[0];
    const float* y = (const float*)d_in[1];
    float* out = (float*)d_out;

    const int planes = in_sizes[0] / (HH * WW);   // 96
    dim3 grid(HH / CHUNK, planes);                // (16, 96)
    ssim_kernel<<<grid, TPB>>>(x, y, out);
}